// round 2
// baseline (speedup 1.0000x reference)
#include <cuda_runtime.h>
#include <math_constants.h>

#define B_ROWS 8192
#define VOCAB  32000
#define KNEG   5
#define SDOM   100
#define EPSV   1e-10f

// Scalar accumulator for the loss sum. Zero-initialized at load; the init
// kernel re-zeros it every graph replay so kernel_launch is deterministic.
__device__ double g_acc;

__global__ void bo4_init_kernel() { g_acc = 0.0; }

__global__ __launch_bounds__(256)
void bo4_row_kernel(const float* __restrict__ yHat,
                    const float* __restrict__ prob,
                    const int*   __restrict__ y,
                    const int*   __restrict__ ind)
{
    const int b = blockIdx.x;
    const float* row = yHat + (size_t)b * VOCAB;
    const float4* row4 = reinterpret_cast<const float4*>(row);

    // ---- row max over 32000 floats (8000 float4) ----
    float m = -CUDART_INF_F;
    #pragma unroll 4
    for (int i = threadIdx.x; i < VOCAB / 4; i += 256) {
        float4 v = row4[i];
        m = fmaxf(m, fmaxf(fmaxf(v.x, v.y), fmaxf(v.z, v.w)));
    }
    // warp reduce
    #pragma unroll
    for (int o = 16; o > 0; o >>= 1)
        m = fmaxf(m, __shfl_xor_sync(0xFFFFFFFFu, m, o));

    __shared__ float smax[8];
    const int wid = threadIdx.x >> 5;
    if ((threadIdx.x & 31) == 0) smax[wid] = m;
    __syncthreads();

    // ---- per-row tail math on thread 0 ----
    if (threadIdx.x == 0) {
        float mm = smax[0];
        #pragma unroll
        for (int w = 1; w < 8; w++) mm = fmaxf(mm, smax[w]);

        const int yy = y[b];
        const float Yg_l = row[yy] - mm;

        const float* prow = prob + (size_t)yy * SDOM;

        float p[KNEG], comp[KNEG];
        float q = CUDART_INF_F;
        #pragma unroll
        for (int k = 0; k < KNEG; k++) {
            const int idx = ind[b * KNEG + k];   // idx in [0, 100)
            comp[k] = row[idx] - mm;
            p[k]    = 1.0f / prow[idx];
            q       = fminf(q, p[k]);
        }

        float Yg  = q * __expf(Yg_l);
        float sum = Yg;
        float c[KNEG];
        #pragma unroll
        for (int k = 0; k < KNEG; k++) {
            c[k] = p[k] * __expf(comp[k]);
            sum += c[k];
        }
        const float inv = 1.0f / sum;

        float term = __logf(Yg * inv + EPSV);
        #pragma unroll
        for (int k = 0; k < KNEG; k++)
            term += __logf(1.0f - c[k] * inv + EPSV);

        atomicAdd(&g_acc, (double)term);
    }
}

__global__ void bo4_final_kernel(float* __restrict__ out)
{
    out[0] = (float)(-g_acc / (double)(B_ROWS * (KNEG + 1)));
}

extern "C" void kernel_launch(void* const* d_in, const int* in_sizes, int n_in,
                              void* d_out, int out_size)
{
    const float* yHat = (const float*)d_in[0];   // [B, V] fp32
    const float* prob = (const float*)d_in[1];   // [V, S] fp32
    const int*   y    = (const int*)  d_in[2];   // [B]    int32
    const int*   ind  = (const int*)  d_in[3];   // [B, K] int32

    bo4_init_kernel<<<1, 1>>>();
    bo4_row_kernel<<<B_ROWS, 256>>>(yHat, prob, y, ind);
    bo4_final_kernel<<<1, 1>>>((float*)d_out);
}

// round 5
// speedup vs baseline: 1.0257x; 1.0257x over previous
#include <cuda_runtime.h>
#include <math_constants.h>

#define B_ROWS 8192
#define VOCAB  32000
#define KNEG   5
#define SDOM   100
#define EPSV   1e-10f

// Self-resetting accumulator state: starts zero (static init); the LAST block
// of each launch reads it, writes the output, and resets it back to zero so
// every graph replay sees identical initial state. No separate init kernel.
__device__ double       g_acc   = 0.0;
__device__ unsigned int g_count = 0;

__global__ __launch_bounds__(256)
void bo4_fused_kernel(const float* __restrict__ yHat,
                      const float* __restrict__ prob,
                      const int*   __restrict__ y,
                      const int*   __restrict__ ind,
                      float*       __restrict__ out)
{
    const int b = blockIdx.x;
    const float* row = yHat + (size_t)b * VOCAB;
    const float4* row4 = reinterpret_cast<const float4*>(row);

    // ---- row max over 32000 floats (8000 float4), streaming (no-reuse) ----
    float m = -CUDART_INF_F;
    #pragma unroll 4
    for (int i = threadIdx.x; i < VOCAB / 4; i += 256) {
        float4 v = __ldcs(row4 + i);     // evict-first: 1 GB one-pass stream
        m = fmaxf(m, fmaxf(fmaxf(v.x, v.y), fmaxf(v.z, v.w)));
    }
    #pragma unroll
    for (int o = 16; o > 0; o >>= 1)
        m = fmaxf(m, __shfl_xor_sync(0xFFFFFFFFu, m, o));

    __shared__ float smax[8];
    const int wid = threadIdx.x >> 5;
    if ((threadIdx.x & 31) == 0) smax[wid] = m;
    __syncthreads();

    // ---- per-row tail on thread 0, then last-block finalize ----
    if (threadIdx.x == 0) {
        float mm = smax[0];
        #pragma unroll
        for (int w = 1; w < 8; w++) mm = fmaxf(mm, smax[w]);

        const int yy = y[b];
        const float Yg_l = __ldg(row + yy) - mm;
        const float* prow = prob + (size_t)yy * SDOM;

        float p[KNEG], comp[KNEG];
        float q = CUDART_INF_F;
        #pragma unroll
        for (int k = 0; k < KNEG; k++) {
            const int idx = __ldg(ind + b * KNEG + k);   // idx in [0, 100)
            comp[k] = __ldg(row + idx) - mm;
            p[k]    = 1.0f / __ldg(prow + idx);
            q       = fminf(q, p[k]);
        }

        float Yg  = q * __expf(Yg_l);
        float sum = Yg;
        float c[KNEG];
        #pragma unroll
        for (int k = 0; k < KNEG; k++) {
            c[k] = p[k] * __expf(comp[k]);
            sum += c[k];
        }
        const float inv = 1.0f / sum;

        float term = __logf(Yg * inv + EPSV);
        #pragma unroll
        for (int k = 0; k < KNEG; k++)
            term += __logf(1.0f - c[k] * inv + EPSV);

        atomicAdd(&g_acc, (double)term);

        // last-block-done: the 8192nd arriver finalizes and resets state
        __threadfence();
        unsigned int t = atomicAdd(&g_count, 1u);
        if (t == (unsigned)(B_ROWS - 1)) {
            out[0] = (float)(-g_acc / (double)(B_ROWS * (KNEG + 1)));
            g_acc   = 0.0;        // restore initial state for next replay
            g_count = 0u;
            __threadfence();
        }
    }
}

extern "C" void kernel_launch(void* const* d_in, const int* in_sizes, int n_in,
                              void* d_out, int out_size)
{
    const float* yHat = (const float*)d_in[0];   // [B, V] fp32
    const float* prob = (const float*)d_in[1];   // [V, S] fp32
    const int*   y    = (const int*)  d_in[2];   // [B]    int32
    const int*   ind  = (const int*)  d_in[3];   // [B, K] int32

    bo4_fused_kernel<<<B_ROWS, 256>>>(yHat, prob, y, ind, (float*)d_out);
}